// round 1
// baseline (speedup 1.0000x reference)
#include <cuda_runtime.h>
#include <math.h>

// Problem constants
#define D_MODEL 1024
#define N_HEADS 16
#define DKH     64           // head dim
#define BATCH   2
#define SEQ     2048
#define M_TOT   (BATCH * SEQ)   // 4096

// ---------------- scratch (no allocation allowed -> device globals) ----------
__device__ float g_Q[M_TOT * D_MODEL];
__device__ float g_K[M_TOT * D_MODEL];
__device__ float g_V[M_TOT * D_MODEL];
__device__ float g_A[M_TOT * D_MODEL];   // attention output (heads concatenated)

// ---------------- GEMM: Y[m][n] = sum_k X[m][k] * W[n][k] + bias[n] ----------
// X: [M,K] row-major, W: [N,K] row-major (torch weight), both K-contiguous.
#define BM 128
#define BN 128
#define BKK 8

__global__ __launch_bounds__(256) void gemm_bias_kernel(
    const float* __restrict__ X, const float* __restrict__ W,
    const float* __restrict__ bias, float* __restrict__ Y,
    int M, int N, int K)
{
    __shared__ float As[BKK][BM];
    __shared__ float Bs[BKK][BN];

    const int tid = threadIdx.x;
    const int tx  = tid & 15;        // 0..15 (col groups)
    const int ty  = tid >> 4;        // 0..15 (row groups)
    const int bm  = blockIdx.y * BM;
    const int bn  = blockIdx.x * BN;

    // global->smem load mapping: each thread one float4 from X and one from W per BKK
    const int lrow = tid >> 1;       // 0..127
    const int lk   = (tid & 1) * 4;  // 0 or 4
    const float* Xp = X + (size_t)(bm + lrow) * K + lk;
    const float* Wp = W + (size_t)(bn + lrow) * K + lk;

    float acc[8][8];
#pragma unroll
    for (int i = 0; i < 8; i++)
#pragma unroll
        for (int j = 0; j < 8; j++) acc[i][j] = 0.f;

    for (int k0 = 0; k0 < K; k0 += BKK) {
        float4 xa = *(const float4*)(Xp + k0);
        float4 wb = *(const float4*)(Wp + k0);
        As[lk + 0][lrow] = xa.x; As[lk + 1][lrow] = xa.y;
        As[lk + 2][lrow] = xa.z; As[lk + 3][lrow] = xa.w;
        Bs[lk + 0][lrow] = wb.x; Bs[lk + 1][lrow] = wb.y;
        Bs[lk + 2][lrow] = wb.z; Bs[lk + 3][lrow] = wb.w;
        __syncthreads();

#pragma unroll
        for (int kk = 0; kk < BKK; kk++) {
            float a[8], b[8];
            *(float4*)(a)     = *(const float4*)&As[kk][ty * 4];
            *(float4*)(a + 4) = *(const float4*)&As[kk][64 + ty * 4];
            *(float4*)(b)     = *(const float4*)&Bs[kk][tx * 4];
            *(float4*)(b + 4) = *(const float4*)&Bs[kk][64 + tx * 4];
#pragma unroll
            for (int i = 0; i < 8; i++)
#pragma unroll
                for (int j = 0; j < 8; j++)
                    acc[i][j] += a[i] * b[j];
        }
        __syncthreads();
    }

#pragma unroll
    for (int i = 0; i < 8; i++) {
        int r = bm + ((i < 4) ? (ty * 4 + i) : (64 + ty * 4 + i - 4));
#pragma unroll
        for (int j = 0; j < 8; j++) {
            int c = bn + ((j < 4) ? (tx * 4 + j) : (64 + tx * 4 + j - 4));
            Y[(size_t)r * N + c] = acc[i][j] + bias[c];
        }
    }
}

// ---------------- causal flash attention, fp32 -------------------------------
// One block: 64 query rows of one (b,h). Online softmax, K/V tiles of 64.
#define BQ   64
#define BKV  64
#define SPAD 65   // padded row stride (odd -> conflict-free scalar LDS)

#define FLASH_SMEM (4 * BQ * SPAD * 4)   // Qs, Ks, Vs, Ps

__global__ __launch_bounds__(256) void flash_kernel()
{
    extern __shared__ float sm[];
    float* Qs = sm;                  // [BQ][SPAD]
    float* Ks = Qs + BQ * SPAD;      // [BKV][SPAD]
    float* Vs = Ks + BKV * SPAD;     // [BKV][SPAD]
    float* Ps = Vs + BKV * SPAD;     // [BQ][SPAD]

    const int tid = threadIdx.x;
    const int tx  = tid & 15;        // key/dcol group
    const int ty  = tid >> 4;        // query-row group
    const int qt  = blockIdx.x;      // query tile
    const int bh  = blockIdx.y;
    const int b   = bh >> 4;
    const int h   = bh & 15;
    const int qbase = qt * BQ;

    const size_t base = (size_t)b * SEQ * D_MODEL + (size_t)h * DKH;
    const float* Qg = g_Q + base;
    const float* Kg = g_K + base;
    const float* Vg = g_V + base;

    // load Q tile [64][64]
#pragma unroll
    for (int t = 0; t < 16; t++) {
        int idx = tid + t * 256;
        int r = idx >> 6, d = idx & 63;
        Qs[r * SPAD + d] = Qg[(size_t)(qbase + r) * D_MODEL + d];
    }
    __syncthreads();

    float mrow[4], lrow[4], O[4][4];
#pragma unroll
    for (int i = 0; i < 4; i++) {
        mrow[i] = -1e30f; lrow[i] = 0.f;
#pragma unroll
        for (int j = 0; j < 4; j++) O[i][j] = 0.f;
    }

    const int nkt = qt + 1;           // causal: tiles 0..qt
    for (int kt = 0; kt < nkt; kt++) {
        const int kbase = kt * BKV;
        // load K,V tiles
#pragma unroll
        for (int t = 0; t < 16; t++) {
            int idx = tid + t * 256;
            int r = idx >> 6, d = idx & 63;
            Ks[r * SPAD + d] = Kg[(size_t)(kbase + r) * D_MODEL + d];
            Vs[r * SPAD + d] = Vg[(size_t)(kbase + r) * D_MODEL + d];
        }
        __syncthreads();

        // scores S = Q K^T (4x4 per thread)
        float s[4][4];
#pragma unroll
        for (int i = 0; i < 4; i++)
#pragma unroll
            for (int j = 0; j < 4; j++) s[i][j] = 0.f;

#pragma unroll 8
        for (int d = 0; d < DKH; d++) {
            float a[4], bb[4];
#pragma unroll
            for (int i = 0; i < 4; i++) a[i]  = Qs[(ty * 4 + i) * SPAD + d];
#pragma unroll
            for (int j = 0; j < 4; j++) bb[j] = Ks[(tx * 4 + j) * SPAD + d];
#pragma unroll
            for (int i = 0; i < 4; i++)
#pragma unroll
                for (int j = 0; j < 4; j++)
                    s[i][j] += a[i] * bb[j];
        }

        // scale + causal mask
#pragma unroll
        for (int i = 0; i < 4; i++) {
            int gq = qbase + ty * 4 + i;
#pragma unroll
            for (int j = 0; j < 4; j++) {
                int gk = kbase + tx * 4 + j;
                float v = s[i][j] * 0.125f;       // 1/sqrt(64)
                s[i][j] = (gk > gq) ? -1e30f : v;
            }
        }

        // online softmax update (rows shared by 16 threads with same ty)
        float mnew[4], fac[4];
#pragma unroll
        for (int i = 0; i < 4; i++) {
            float mx = fmaxf(fmaxf(s[i][0], s[i][1]), fmaxf(s[i][2], s[i][3]));
#pragma unroll
            for (int off = 8; off >= 1; off >>= 1)
                mx = fmaxf(mx, __shfl_xor_sync(0xffffffffu, mx, off, 16));
            mnew[i] = fmaxf(mrow[i], mx);
            float sum = 0.f;
#pragma unroll
            for (int j = 0; j < 4; j++) {
                float p = __expf(s[i][j] - mnew[i]);
                s[i][j] = p;
                sum += p;
            }
#pragma unroll
            for (int off = 8; off >= 1; off >>= 1)
                sum += __shfl_xor_sync(0xffffffffu, sum, off, 16);
            fac[i]  = __expf(mrow[i] - mnew[i]);
            lrow[i] = lrow[i] * fac[i] + sum;
            mrow[i] = mnew[i];
#pragma unroll
            for (int j = 0; j < 4; j++) O[i][j] *= fac[i];
        }

        // stage P to smem
#pragma unroll
        for (int i = 0; i < 4; i++)
#pragma unroll
            for (int j = 0; j < 4; j++)
                Ps[(ty * 4 + i) * SPAD + tx * 4 + j] = s[i][j];
        __syncthreads();

        // O += P V    (tx now indexes d-columns of output)
#pragma unroll 8
        for (int k2 = 0; k2 < BKV; k2++) {
            float a[4], bb[4];
#pragma unroll
            for (int i = 0; i < 4; i++) a[i]  = Ps[(ty * 4 + i) * SPAD + k2];
#pragma unroll
            for (int j = 0; j < 4; j++) bb[j] = Vs[k2 * SPAD + tx * 4 + j];
#pragma unroll
            for (int i = 0; i < 4; i++)
#pragma unroll
                for (int j = 0; j < 4; j++)
                    O[i][j] += a[i] * bb[j];
        }
        __syncthreads();
    }

    // normalize and write
    float* Ag = g_A + base;
#pragma unroll
    for (int i = 0; i < 4; i++) {
        float inv = 1.0f / lrow[i];
        int r = qbase + ty * 4 + i;
#pragma unroll
        for (int j = 0; j < 4; j++)
            Ag[(size_t)r * D_MODEL + tx * 4 + j] = O[i][j] * inv;
    }
}

// ---------------- launch -----------------------------------------------------
extern "C" void kernel_launch(void* const* d_in, const int* in_sizes, int n_in,
                              void* d_out, int out_size)
{
    (void)in_sizes; (void)n_in; (void)out_size;
    const float* in_Q = (const float*)d_in[0];
    const float* in_K = (const float*)d_in[1];
    const float* in_V = (const float*)d_in[2];
    const float* Wq   = (const float*)d_in[3];
    const float* bq   = (const float*)d_in[4];
    const float* Wk   = (const float*)d_in[5];
    const float* bk   = (const float*)d_in[6];
    const float* Wv   = (const float*)d_in[7];
    const float* bv   = (const float*)d_in[8];
    const float* Wo   = (const float*)d_in[9];
    const float* bo   = (const float*)d_in[10];
    float* out = (float*)d_out;

    float *qp, *kp, *vp, *ap;
    cudaGetSymbolAddress((void**)&qp, g_Q);
    cudaGetSymbolAddress((void**)&kp, g_K);
    cudaGetSymbolAddress((void**)&vp, g_V);
    cudaGetSymbolAddress((void**)&ap, g_A);

    cudaFuncSetAttribute(flash_kernel,
                         cudaFuncAttributeMaxDynamicSharedMemorySize, FLASH_SMEM);

    dim3 gemm_grid(D_MODEL / BN, M_TOT / BM);   // (8, 32)
    dim3 tb(256);

    gemm_bias_kernel<<<gemm_grid, tb>>>(in_Q, Wq, bq, qp, M_TOT, D_MODEL, D_MODEL);
    gemm_bias_kernel<<<gemm_grid, tb>>>(in_K, Wk, bk, kp, M_TOT, D_MODEL, D_MODEL);
    gemm_bias_kernel<<<gemm_grid, tb>>>(in_V, Wv, bv, vp, M_TOT, D_MODEL, D_MODEL);

    dim3 fgrid(SEQ / BQ, BATCH * N_HEADS);      // (32, 32)
    flash_kernel<<<fgrid, tb, FLASH_SMEM>>>();

    gemm_bias_kernel<<<gemm_grid, tb>>>(ap, Wo, bo, out, M_TOT, D_MODEL, D_MODEL);
}

// round 5
// speedup vs baseline: 3.2713x; 3.2713x over previous
#include <cuda_runtime.h>
#include <math.h>

// Problem constants
#define D_MODEL 1024
#define N_HEADS 16
#define DKH     64
#define BATCH   2
#define SEQ     2048
#define M_TOT   (BATCH * SEQ)   // 4096

// ---------------- scratch ----------------------------------------------------
__device__ float g_Q[M_TOT * D_MODEL];
__device__ float g_K[M_TOT * D_MODEL];
__device__ float g_V[M_TOT * D_MODEL];
__device__ float g_A[M_TOT * D_MODEL];

// ---------------- tf32 helpers ----------------------------------------------
__device__ __forceinline__ unsigned f2tf(float f) {
    unsigned r;
    asm("cvt.rna.tf32.f32 %0, %1;" : "=r"(r) : "f"(f));
    return r;
}

__device__ __forceinline__ void mma_tf32(float* c, const unsigned* a, const unsigned* b) {
    asm volatile(
        "mma.sync.aligned.m16n8k8.row.col.f32.tf32.tf32.f32 "
        "{%0,%1,%2,%3}, {%4,%5,%6,%7}, {%8,%9}, {%0,%1,%2,%3};"
        : "+f"(c[0]), "+f"(c[1]), "+f"(c[2]), "+f"(c[3])
        : "r"(a[0]), "r"(a[1]), "r"(a[2]), "r"(a[3]), "r"(b[0]), "r"(b[1]));
}

// ---------------- GEMM: Y = X[M,K] * W[N,K]^T + bias -------------------------
// Block 256 thr = 8 warps, tile 128x128, BK=32. Warp grid 2(m)x4(n), warp tile 64x32.
#define GSTR 36   // smem row stride (36 % 32 == 4 -> conflict-free frag loads)

__global__ __launch_bounds__(256) void gemm_tf32_kernel(
    const float* __restrict__ X, const float* __restrict__ W,
    const float* __restrict__ bias, float* __restrict__ Y,
    int M, int N, int K)
{
    __shared__ unsigned As[128 * GSTR];
    __shared__ unsigned Bs[128 * GSTR];

    const int tid  = threadIdx.x;
    const int warp = tid >> 5, lane = tid & 31;
    const int wm = warp >> 2, wn = warp & 3;
    const int g  = lane >> 2, tg = lane & 3;
    const int bm = blockIdx.y * 128, bn = blockIdx.x * 128;

    const int lr = tid >> 3;        // 0..31
    const int lc = (tid & 7) * 4;   // 0..28

    float c[4][4][4];
#pragma unroll
    for (int mf = 0; mf < 4; mf++)
#pragma unroll
        for (int nf = 0; nf < 4; nf++)
#pragma unroll
            for (int k = 0; k < 4; k++) c[mf][nf][k] = 0.f;

    for (int k0 = 0; k0 < K; k0 += 32) {
        // stage X tile (128x32) and W tile (128x32), convert to tf32
#pragma unroll
        for (int i = 0; i < 4; i++) {
            int r = lr + 32 * i;
            float4 xv = *(const float4*)(X + (size_t)(bm + r) * K + k0 + lc);
            float4 wv = *(const float4*)(W + (size_t)(bn + r) * K + k0 + lc);
            As[r * GSTR + lc + 0] = f2tf(xv.x); As[r * GSTR + lc + 1] = f2tf(xv.y);
            As[r * GSTR + lc + 2] = f2tf(xv.z); As[r * GSTR + lc + 3] = f2tf(xv.w);
            Bs[r * GSTR + lc + 0] = f2tf(wv.x); Bs[r * GSTR + lc + 1] = f2tf(wv.y);
            Bs[r * GSTR + lc + 2] = f2tf(wv.z); Bs[r * GSTR + lc + 3] = f2tf(wv.w);
        }
        __syncthreads();

#pragma unroll
        for (int ks = 0; ks < 4; ks++) {
            unsigned a[4][4], b[4][2];
#pragma unroll
            for (int mf = 0; mf < 4; mf++) {
                int row = wm * 64 + mf * 16;
                a[mf][0] = As[(row + g    ) * GSTR + ks * 8 + tg    ];
                a[mf][1] = As[(row + g + 8) * GSTR + ks * 8 + tg    ];
                a[mf][2] = As[(row + g    ) * GSTR + ks * 8 + tg + 4];
                a[mf][3] = As[(row + g + 8) * GSTR + ks * 8 + tg + 4];
            }
#pragma unroll
            for (int nf = 0; nf < 4; nf++) {
                int col = wn * 32 + nf * 8 + g;
                b[nf][0] = Bs[col * GSTR + ks * 8 + tg    ];
                b[nf][1] = Bs[col * GSTR + ks * 8 + tg + 4];
            }
#pragma unroll
            for (int mf = 0; mf < 4; mf++)
#pragma unroll
                for (int nf = 0; nf < 4; nf++)
                    mma_tf32(c[mf][nf], a[mf], b[nf]);
        }
        __syncthreads();
    }

    // epilogue: bias + store (float2 per row-pair)
#pragma unroll
    for (int mf = 0; mf < 4; mf++) {
#pragma unroll
        for (int nf = 0; nf < 4; nf++) {
            int row = bm + wm * 64 + mf * 16 + g;
            int col = bn + wn * 32 + nf * 8 + 2 * tg;
            float b0 = bias[col], b1 = bias[col + 1];
            *(float2*)(Y + (size_t)row * N + col) =
                make_float2(c[mf][nf][0] + b0, c[mf][nf][1] + b1);
            *(float2*)(Y + (size_t)(row + 8) * N + col) =
                make_float2(c[mf][nf][2] + b0, c[mf][nf][3] + b1);
        }
    }
}

// ---------------- flash attention with tf32 MMA ------------------------------
// Block: 128 thr = 4 warps, 64 q-rows per block (16 per warp), KV tiles of 64.
// Smem: Ps[64][68] (also Q staging), Ks[64][68], Vs[64][72] (tf32 bits).
#define PSTR 68   // g-indexed rows: 68 % 32 == 4
#define VSTR 72   // tg-indexed rows: 72 % 32 == 8
#define FLASH_SMEM ((64 * PSTR * 2 + 64 * VSTR) * 4)

__global__ __launch_bounds__(128) void flash_tf32_kernel()
{
    extern __shared__ unsigned sm[];
    unsigned* Ps = sm;                   // [64][PSTR]  (Q staging, then P)
    unsigned* Ks = Ps + 64 * PSTR;       // [64][PSTR]
    unsigned* Vs = Ks + 64 * PSTR;       // [64][VSTR]

    const int tid  = threadIdx.x;
    const int warp = tid >> 5, lane = tid & 31;
    const int g = lane >> 2, tg = lane & 3;
    const int qt = blockIdx.x;
    const int bh = blockIdx.y;
    const int b  = bh >> 4, h = bh & 15;
    const int qbase = qt * 64;

    const size_t base = (size_t)b * SEQ * D_MODEL + (size_t)h * DKH;
    const float* Qg = g_Q + base;
    const float* Kg = g_K + base;
    const float* Vg = g_V + base;

    const int sr = tid >> 4;         // staging row 0..7
    const int sc = (tid & 15) * 4;   // staging col 0..60

    // ---- stage Q, extract Q fragments into registers ----
#pragma unroll
    for (int p = 0; p < 8; p++) {
        int r = sr + 8 * p;
        float4 v = *(const float4*)(Qg + (size_t)(qbase + r) * D_MODEL + sc);
        Ps[r * PSTR + sc + 0] = f2tf(v.x); Ps[r * PSTR + sc + 1] = f2tf(v.y);
        Ps[r * PSTR + sc + 2] = f2tf(v.z); Ps[r * PSTR + sc + 3] = f2tf(v.w);
    }
    __syncthreads();

    unsigned qf[8][4];
    {
        int row = warp * 16;
#pragma unroll
        for (int ks = 0; ks < 8; ks++) {
            qf[ks][0] = Ps[(row + g    ) * PSTR + ks * 8 + tg    ];
            qf[ks][1] = Ps[(row + g + 8) * PSTR + ks * 8 + tg    ];
            qf[ks][2] = Ps[(row + g    ) * PSTR + ks * 8 + tg + 4];
            qf[ks][3] = Ps[(row + g + 8) * PSTR + ks * 8 + tg + 4];
        }
    }

    float O[8][4];
#pragma unroll
    for (int nf = 0; nf < 8; nf++)
#pragma unroll
        for (int k = 0; k < 4; k++) O[nf][k] = 0.f;
    float m0 = -1e30f, m1 = -1e30f, l0 = 0.f, l1 = 0.f;

    const int q0 = qbase + warp * 16 + g;       // global q for c0/c1
    const int q1 = q0 + 8;                      // global q for c2/c3

    const int nkt = qt + 1;
    for (int kt = 0; kt < nkt; kt++) {
        const int kbase = kt * 64;
        // ---- stage K,V tiles ----
        __syncthreads();
#pragma unroll
        for (int p = 0; p < 8; p++) {
            int r = sr + 8 * p;
            float4 kv = *(const float4*)(Kg + (size_t)(kbase + r) * D_MODEL + sc);
            float4 vv = *(const float4*)(Vg + (size_t)(kbase + r) * D_MODEL + sc);
            Ks[r * PSTR + sc + 0] = f2tf(kv.x); Ks[r * PSTR + sc + 1] = f2tf(kv.y);
            Ks[r * PSTR + sc + 2] = f2tf(kv.z); Ks[r * PSTR + sc + 3] = f2tf(kv.w);
            Vs[r * VSTR + sc + 0] = f2tf(vv.x); Vs[r * VSTR + sc + 1] = f2tf(vv.y);
            Vs[r * VSTR + sc + 2] = f2tf(vv.z); Vs[r * VSTR + sc + 3] = f2tf(vv.w);
        }
        __syncthreads();

        // ---- S = Q K^T  (m16 x n64) ----
        float S[8][4];
#pragma unroll
        for (int nf = 0; nf < 8; nf++)
#pragma unroll
            for (int k = 0; k < 4; k++) S[nf][k] = 0.f;

#pragma unroll
        for (int ks = 0; ks < 8; ks++) {
#pragma unroll
            for (int nf = 0; nf < 8; nf++) {
                unsigned bb[2];
                bb[0] = Ks[(nf * 8 + g) * PSTR + ks * 8 + tg    ];
                bb[1] = Ks[(nf * 8 + g) * PSTR + ks * 8 + tg + 4];
                mma_tf32(S[nf], qf[ks], bb);
            }
        }

        // ---- scale + causal mask ----
        const bool diag = (kt == qt);
#pragma unroll
        for (int nf = 0; nf < 8; nf++) {
            int kc0 = kbase + nf * 8 + 2 * tg;
            S[nf][0] *= 0.125f; S[nf][1] *= 0.125f;
            S[nf][2] *= 0.125f; S[nf][3] *= 0.125f;
            if (diag) {
                if (kc0     > q0) S[nf][0] = -1e30f;
                if (kc0 + 1 > q0) S[nf][1] = -1e30f;
                if (kc0     > q1) S[nf][2] = -1e30f;
                if (kc0 + 1 > q1) S[nf][3] = -1e30f;
            }
        }

        // ---- online softmax (rows r0=g, r1=g+8 shared by 4 lanes/quad) ----
        float mx0 = -1e30f, mx1 = -1e30f;
#pragma unroll
        for (int nf = 0; nf < 8; nf++) {
            mx0 = fmaxf(mx0, fmaxf(S[nf][0], S[nf][1]));
            mx1 = fmaxf(mx1, fmaxf(S[nf][2], S[nf][3]));
        }
        mx0 = fmaxf(mx0, __shfl_xor_sync(0xffffffffu, mx0, 1));
        mx0 = fmaxf(mx0, __shfl_xor_sync(0xffffffffu, mx0, 2));
        mx1 = fmaxf(mx1, __shfl_xor_sync(0xffffffffu, mx1, 1));
        mx1 = fmaxf(mx1, __shfl_xor_sync(0xffffffffu, mx1, 2));

        float mn0 = fmaxf(m0, mx0), mn1 = fmaxf(m1, mx1);
        float fac0 = __expf(m0 - mn0), fac1 = __expf(m1 - mn1);

        float s0 = 0.f, s1 = 0.f;
#pragma unroll
        for (int nf = 0; nf < 8; nf++) {
            S[nf][0] = __expf(S[nf][0] - mn0);
            S[nf][1] = __expf(S[nf][1] - mn0);
            S[nf][2] = __expf(S[nf][2] - mn1);
            S[nf][3] = __expf(S[nf][3] - mn1);
            s0 += S[nf][0] + S[nf][1];
            s1 += S[nf][2] + S[nf][3];
        }
        s0 += __shfl_xor_sync(0xffffffffu, s0, 1);
        s0 += __shfl_xor_sync(0xffffffffu, s0, 2);
        s1 += __shfl_xor_sync(0xffffffffu, s1, 1);
        s1 += __shfl_xor_sync(0xffffffffu, s1, 2);

        l0 = l0 * fac0 + s0; l1 = l1 * fac1 + s1;
        m0 = mn0; m1 = mn1;
#pragma unroll
        for (int nf = 0; nf < 8; nf++) {
            O[nf][0] *= fac0; O[nf][1] *= fac0;
            O[nf][2] *= fac1; O[nf][3] *= fac1;
        }

        // ---- P -> smem (per-warp region), then O += P V ----
        {
            int row = warp * 16;
#pragma unroll
            for (int nf = 0; nf < 8; nf++) {
                int col = nf * 8 + 2 * tg;
                Ps[(row + g    ) * PSTR + col    ] = f2tf(S[nf][0]);
                Ps[(row + g    ) * PSTR + col + 1] = f2tf(S[nf][1]);
                Ps[(row + g + 8) * PSTR + col    ] = f2tf(S[nf][2]);
                Ps[(row + g + 8) * PSTR + col + 1] = f2tf(S[nf][3]);
            }
        }
        __syncwarp();

#pragma unroll
        for (int ks = 0; ks < 8; ks++) {
            unsigned a[4];
            int row = warp * 16;
            a[0] = Ps[(row + g    ) * PSTR + ks * 8 + tg    ];
            a[1] = Ps[(row + g + 8) * PSTR + ks * 8 + tg    ];
            a[2] = Ps[(row + g    ) * PSTR + ks * 8 + tg + 4];
            a[3] = Ps[(row + g + 8) * PSTR + ks * 8 + tg + 4];
#pragma unroll
            for (int nf = 0; nf < 8; nf++) {
                unsigned bb[2];
                bb[0] = Vs[(ks * 8 + tg    ) * VSTR + nf * 8 + g];
                bb[1] = Vs[(ks * 8 + tg + 4) * VSTR + nf * 8 + g];
                mma_tf32(O[nf], a, bb);
            }
        }
        __syncwarp();
    }

    // ---- normalize + write ----
    float inv0 = 1.0f / l0, inv1 = 1.0f / l1;
    float* Ag = g_A + base;
#pragma unroll
    for (int nf = 0; nf < 8; nf++) {
        int col = nf * 8 + 2 * tg;
        *(float2*)(Ag + (size_t)q0 * D_MODEL + col) =
            make_float2(O[nf][0] * inv0, O[nf][1] * inv0);
        *(float2*)(Ag + (size_t)q1 * D_MODEL + col) =
            make_float2(O[nf][2] * inv1, O[nf][3] * inv1);
    }
}

// ---------------- launch -----------------------------------------------------
extern "C" void kernel_launch(void* const* d_in, const int* in_sizes, int n_in,
                              void* d_out, int out_size)
{
    (void)in_sizes; (void)n_in; (void)out_size;
    const float* in_Q = (const float*)d_in[0];
    const float* in_K = (const float*)d_in[1];
    const float* in_V = (const float*)d_in[2];
    const float* Wq   = (const float*)d_in[3];
    const float* bq   = (const float*)d_in[4];
    const float* Wk   = (const float*)d_in[5];
    const float* bk   = (const float*)d_in[6];
    const float* Wv   = (const float*)d_in[7];
    const float* bv   = (const float*)d_in[8];
    const float* Wo   = (const float*)d_in[9];
    const float* bo   = (const float*)d_in[10];
    float* out = (float*)d_out;

    float *qp, *kp, *vp, *ap;
    cudaGetSymbolAddress((void**)&qp, g_Q);
    cudaGetSymbolAddress((void**)&kp, g_K);
    cudaGetSymbolAddress((void**)&vp, g_V);
    cudaGetSymbolAddress((void**)&ap, g_A);

    cudaFuncSetAttribute(flash_tf32_kernel,
                         cudaFuncAttributeMaxDynamicSharedMemorySize, FLASH_SMEM);

    dim3 gemm_grid(D_MODEL / 128, M_TOT / 128);   // (8, 32)

    gemm_tf32_kernel<<<gemm_grid, 256>>>(in_Q, Wq, bq, qp, M_TOT, D_MODEL, D_MODEL);
    gemm_tf32_kernel<<<gemm_grid, 256>>>(in_K, Wk, bk, kp, M_TOT, D_MODEL, D_MODEL);
    gemm_tf32_kernel<<<gemm_grid, 256>>>(in_V, Wv, bv, vp, M_TOT, D_MODEL, D_MODEL);

    dim3 fgrid(SEQ / 64, BATCH * N_HEADS);        // (32, 32)
    flash_tf32_kernel<<<fgrid, 128, FLASH_SMEM>>>();

    gemm_tf32_kernel<<<gemm_grid, 256>>>(ap, Wo, bo, out, M_TOT, D_MODEL, D_MODEL);
}